// round 9
// baseline (speedup 1.0000x reference)
#include <cuda_runtime.h>
#include <cstddef>

#define BM 128
#define BN 128
#define BK 16
#define TM 8
#define TN 8

constexpr int Bsz = 4;
constexpr int S   = 4096;
constexpr int D   = 256;
constexpr int C   = 8921;

// ---------------------------------------------------------------------------
// Kernel 1: scores[b][c][s] = sum_d W[c][d] * x[b][s][d]   (NT GEMM)
// Writes RAW scores into the attention region of d_out.
// ---------------------------------------------------------------------------
__global__ __launch_bounds__(256, 2)
void k_scores(const float* __restrict__ x, const float* __restrict__ W,
              float* __restrict__ att)
{
    const int b     = blockIdx.z;
    const int cBase = blockIdx.y * BM;
    const int sBase = blockIdx.x * BN;

    const float* xb  = x   + (size_t)b * S * D;
    float*       out = att + (size_t)b * C * S;

    __shared__ float As[BK][BM];
    __shared__ float Bs[BK][BN];

    const int tid = threadIdx.x;          // 256 threads
    const int tx  = tid & 15;             // 16 x 16 thread grid
    const int ty  = tid >> 4;

    float acc[TM][TN];
    #pragma unroll
    for (int i = 0; i < TM; i++)
        #pragma unroll
        for (int j = 0; j < TN; j++) acc[i][j] = 0.0f;

    for (int k0 = 0; k0 < D; k0 += BK) {
        // Load A tile: W rows cBase..+127, cols k0..+15 (row stride D)
        #pragma unroll
        for (int l = 0; l < 2; l++) {
            int i   = tid + l * 256;      // 0..511 float4 loads
            int row = i >> 2;
            int kc  = (i & 3) * 4;
            int c   = cBase + row;
            float4 v = (c < C) ? *(const float4*)&W[(size_t)c * D + k0 + kc]
                               : make_float4(0.f, 0.f, 0.f, 0.f);
            As[kc + 0][row] = v.x; As[kc + 1][row] = v.y;
            As[kc + 2][row] = v.z; As[kc + 3][row] = v.w;
        }
        // Load B tile: x rows sBase..+127, cols k0..+15 (row stride D)
        #pragma unroll
        for (int l = 0; l < 2; l++) {
            int i   = tid + l * 256;
            int row = i >> 2;
            int kc  = (i & 3) * 4;
            float4 v = *(const float4*)&xb[(size_t)(sBase + row) * D + k0 + kc];
            Bs[kc + 0][row] = v.x; Bs[kc + 1][row] = v.y;
            Bs[kc + 2][row] = v.z; Bs[kc + 3][row] = v.w;
        }
        __syncthreads();

        #pragma unroll
        for (int k = 0; k < BK; k++) {
            float a[TM], bb[TN];
            #pragma unroll
            for (int i = 0; i < TM; i++) a[i]  = As[k][ty * TM + i];
            #pragma unroll
            for (int j = 0; j < TN; j++) bb[j] = Bs[k][tx * TN + j];
            #pragma unroll
            for (int i = 0; i < TM; i++)
                #pragma unroll
                for (int j = 0; j < TN; j++) acc[i][j] += a[i] * bb[j];
        }
        __syncthreads();
    }

    #pragma unroll
    for (int i = 0; i < TM; i++) {
        int c = cBase + ty * TM + i;
        if (c < C) {
            float* o = out + (size_t)c * S + sBase + tx * TN;
            *(float4*)(o)     = make_float4(acc[i][0], acc[i][1], acc[i][2], acc[i][3]);
            *(float4*)(o + 4) = make_float4(acc[i][4], acc[i][5], acc[i][6], acc[i][7]);
        }
    }
}

// ---------------------------------------------------------------------------
// Kernel 2: in-place softmax over S for each (b,c) row.
// ---------------------------------------------------------------------------
__global__ __launch_bounds__(256)
void k_softmax(float* __restrict__ att)
{
    float* p = att + (size_t)blockIdx.x * S;
    const int tid = threadIdx.x;

    float4 v[4];
    float mx = -3.4e38f;
    #pragma unroll
    for (int l = 0; l < 4; l++) {
        v[l] = *(const float4*)&p[(size_t)(tid + l * 256) * 4];
        mx = fmaxf(mx, fmaxf(fmaxf(v[l].x, v[l].y), fmaxf(v[l].z, v[l].w)));
    }

    __shared__ float red[8];
    #pragma unroll
    for (int o = 16; o; o >>= 1) mx = fmaxf(mx, __shfl_xor_sync(0xffffffffu, mx, o));
    if ((tid & 31) == 0) red[tid >> 5] = mx;
    __syncthreads();
    float m = red[0];
    #pragma unroll
    for (int w = 1; w < 8; w++) m = fmaxf(m, red[w]);
    __syncthreads();

    float sum = 0.0f;
    #pragma unroll
    for (int l = 0; l < 4; l++) {
        v[l].x = __expf(v[l].x - m); v[l].y = __expf(v[l].y - m);
        v[l].z = __expf(v[l].z - m); v[l].w = __expf(v[l].w - m);
        sum += (v[l].x + v[l].y) + (v[l].z + v[l].w);
    }
    #pragma unroll
    for (int o = 16; o; o >>= 1) sum += __shfl_xor_sync(0xffffffffu, sum, o);
    if ((tid & 31) == 0) red[tid >> 5] = sum;
    __syncthreads();
    float tot = 0.0f;
    #pragma unroll
    for (int w = 0; w < 8; w++) tot += red[w];
    const float inv = 1.0f / tot;

    #pragma unroll
    for (int l = 0; l < 4; l++) {
        v[l].x *= inv; v[l].y *= inv; v[l].z *= inv; v[l].w *= inv;
        *(float4*)&p[(size_t)(tid + l * 256) * 4] = v[l];
    }
}

// ---------------------------------------------------------------------------
// Kernel 3: logits[b][c][d] = sum_s att[b][c][s] * x[b][s][d]   (NN GEMM)
// ---------------------------------------------------------------------------
__global__ __launch_bounds__(256, 2)
void k_logits(const float* __restrict__ x, const float* __restrict__ att,
              float* __restrict__ logits)
{
    const int b     = blockIdx.z;
    const int cBase = blockIdx.y * BM;
    const int dBase = blockIdx.x * BN;

    const float* xb  = x      + (size_t)b * S * D;
    const float* ab  = att    + (size_t)b * C * S;
    float*       out = logits + (size_t)b * C * D;

    __shared__ float As[BK][BM];
    __shared__ float Bs[BK][BN];

    const int tid = threadIdx.x;
    const int tx  = tid & 15;
    const int ty  = tid >> 4;

    float acc[TM][TN];
    #pragma unroll
    for (int i = 0; i < TM; i++)
        #pragma unroll
        for (int j = 0; j < TN; j++) acc[i][j] = 0.0f;

    for (int k0 = 0; k0 < S; k0 += BK) {
        // A tile: att rows cBase..+127, cols k0..+15 (row stride S)
        #pragma unroll
        for (int l = 0; l < 2; l++) {
            int i   = tid + l * 256;
            int row = i >> 2;
            int kc  = (i & 3) * 4;
            int c   = cBase + row;
            float4 v = (c < C) ? *(const float4*)&ab[(size_t)c * S + k0 + kc]
                               : make_float4(0.f, 0.f, 0.f, 0.f);
            As[kc + 0][row] = v.x; As[kc + 1][row] = v.y;
            As[kc + 2][row] = v.z; As[kc + 3][row] = v.w;
        }
        // B tile: x rows k0..+15, cols dBase..+127 (row stride D) — direct store
        #pragma unroll
        for (int l = 0; l < 2; l++) {
            int i    = tid + l * 256;
            int krow = i >> 5;
            int col  = (i & 31) * 4;
            float4 v = *(const float4*)&xb[(size_t)(k0 + krow) * D + dBase + col];
            *(float4*)&Bs[krow][col] = v;
        }
        __syncthreads();

        #pragma unroll
        for (int k = 0; k < BK; k++) {
            float a[TM], bb[TN];
            #pragma unroll
            for (int i = 0; i < TM; i++) a[i]  = As[k][ty * TM + i];
            #pragma unroll
            for (int j = 0; j < TN; j++) bb[j] = Bs[k][tx * TN + j];
            #pragma unroll
            for (int i = 0; i < TM; i++)
                #pragma unroll
                for (int j = 0; j < TN; j++) acc[i][j] += a[i] * bb[j];
        }
        __syncthreads();
    }

    #pragma unroll
    for (int i = 0; i < TM; i++) {
        int c = cBase + ty * TM + i;
        if (c < C) {
            float* o = out + (size_t)c * D + dBase + tx * TN;
            *(float4*)(o)     = make_float4(acc[i][0], acc[i][1], acc[i][2], acc[i][3]);
            *(float4*)(o + 4) = make_float4(acc[i][4], acc[i][5], acc[i][6], acc[i][7]);
        }
    }
}

// ---------------------------------------------------------------------------
extern "C" void kernel_launch(void* const* d_in, const int* in_sizes, int n_in,
                              void* d_out, int out_size)
{
    const float* x = (const float*)d_in[0];   // [B, S, D]
    const float* W = (const float*)d_in[1];   // [C, D]

    float* logits = (float*)d_out;                         // [B, C, D]
    float* att    = (float*)d_out + (size_t)Bsz * C * D;   // [B, C, S]

    dim3 g1(S / BN, (C + BM - 1) / BM, Bsz);   // 32 x 70 x 4
    k_scores<<<g1, 256>>>(x, W, att);

    k_softmax<<<Bsz * C, 256>>>(att);

    dim3 g2(D / BN, (C + BM - 1) / BM, Bsz);   // 2 x 70 x 4
    k_logits<<<g2, 256>>>(x, att, logits);
}

// round 11
// speedup vs baseline: 1.1608x; 1.1608x over previous
#include <cuda_runtime.h>
#include <cstddef>
#include <cstdint>

constexpr int Bsz = 4, S = 4096, D = 256, C = 8921;
constexpr int CT = (C + 127) / 128;  // 70

// Smem tiles (floats). A-type: [128 rows][32 k + 4 pad]. GEMM2 B: [32 k][128 n + 4 pad].
constexpr int TA   = 128 * 36;            // 4608
constexpr int TB2  = 32 * 132;            // 4224
constexpr int STG1 = 4 * TA;              // Ah, Al, Bh, Bl (GEMM1)
constexpr int STG2 = 2 * TA + 2 * TB2;    // Ah, Al, Bh, Bl (GEMM2)
constexpr int SM1  = 2 * STG1 * 4;        // 147456 B
constexpr int SM2  = 2 * STG2 * 4;        // 141312 B

__device__ __forceinline__ uint32_t t32(float v) {
    uint32_t u;
    asm("cvt.rna.tf32.f32 %0, %1;" : "=r"(u) : "f"(v));
    return u;
}

__device__ __forceinline__ void mma8(float* c, const uint32_t* a, const uint32_t* b) {
    asm volatile(
        "mma.sync.aligned.m16n8k8.row.col.f32.tf32.tf32.f32 "
        "{%0,%1,%2,%3}, {%4,%5,%6,%7}, {%8,%9}, {%0,%1,%2,%3};"
        : "+f"(c[0]), "+f"(c[1]), "+f"(c[2]), "+f"(c[3])
        : "r"(a[0]), "r"(a[1]), "r"(a[2]), "r"(a[3]), "r"(b[0]), "r"(b[1]));
}

// split 4 float4 into tf32 hi/lo and store to smem at [base + j*4]
__device__ __forceinline__ void sts_hl(float* Hh, float* Hl, int base, const float4* f) {
#pragma unroll
    for (int j = 0; j < 4; j++) {
        float4 v = f[j], h, l;
        h.x = __uint_as_float(t32(v.x)); l.x = __uint_as_float(t32(v.x - h.x));
        h.y = __uint_as_float(t32(v.y)); l.y = __uint_as_float(t32(v.y - h.y));
        h.z = __uint_as_float(t32(v.z)); l.z = __uint_as_float(t32(v.z - h.z));
        h.w = __uint_as_float(t32(v.w)); l.w = __uint_as_float(t32(v.w - h.w));
        *(float4*)&Hh[base + j * 4] = h;
        *(float4*)&Hl[base + j * 4] = l;
    }
}

// ---------------------------------------------------------------------------
// GEMM1: scores[b][c][s] = sum_d W[c][d] * x[b][s][d]   (tf32x3, mma.sync)
// ---------------------------------------------------------------------------
__global__ __launch_bounds__(256)
void k_scores(const float* __restrict__ x, const float* __restrict__ W,
              float* __restrict__ att)
{
    extern __shared__ float sm[];
    const int tid = threadIdx.x, lane = tid & 31, warp = tid >> 5;
    const int wm = warp & 1, wn = warp >> 1;        // 2 x 4 warp grid
    const int g = lane >> 2, q = lane & 3;
    const int b = blockIdx.z, cBase = blockIdx.y * 128, sBase = blockIdx.x * 128;

    const float* xb = x + (size_t)b * S * D;

    const int lrow = tid >> 1;                       // 0..127
    const int lcol = (tid & 1) * 16;                 // 0 or 16
    const int arow = cBase + lrow;
    const bool aOK = arow < C;
    const float* aSrc = W + (size_t)(aOK ? arow : 0) * D + lcol;
    const float* bSrc = xb + (size_t)(sBase + lrow) * D + lcol;
    const int sbase = lrow * 36 + lcol;

    float acc[4][4][4];
#pragma unroll
    for (int i = 0; i < 4; i++)
#pragma unroll
        for (int j = 0; j < 4; j++)
#pragma unroll
            for (int k = 0; k < 4; k++) acc[i][j][k] = 0.0f;

    float4 fa[4], fb[4];
#pragma unroll
    for (int j = 0; j < 4; j++) {
        fa[j] = aOK ? __ldg((const float4*)(aSrc + j * 4)) : make_float4(0.f, 0.f, 0.f, 0.f);
        fb[j] = __ldg((const float4*)(bSrc + j * 4));
    }
    sts_hl(sm, sm + TA, sbase, fa);
    sts_hl(sm + 2 * TA, sm + 3 * TA, sbase, fb);
    __syncthreads();

#pragma unroll 1
    for (int it = 0; it < 8; it++) {
        if (it + 1 < 8) {
            const int kk = (it + 1) * 32;
#pragma unroll
            for (int j = 0; j < 4; j++) {
                fa[j] = aOK ? __ldg((const float4*)(aSrc + kk + j * 4)) : make_float4(0.f, 0.f, 0.f, 0.f);
                fb[j] = __ldg((const float4*)(bSrc + kk + j * 4));
            }
        }
        const float* st = sm + (it & 1) * STG1;
        const uint32_t* Ah = (const uint32_t*)st;
        const uint32_t* Al = Ah + TA;
        const uint32_t* Bh = Al + TA;
        const uint32_t* Bl = Bh + TA;

#pragma unroll
        for (int ks = 0; ks < 4; ks++) {
            const int kk = ks * 8;
            uint32_t ah[4][4], al[4][4];
#pragma unroll
            for (int mi = 0; mi < 4; mi++) {
                int i0 = (wm * 64 + mi * 16 + g) * 36 + kk + q;
                ah[mi][0] = Ah[i0];     ah[mi][1] = Ah[i0 + 288];
                ah[mi][2] = Ah[i0 + 4]; ah[mi][3] = Ah[i0 + 292];
                al[mi][0] = Al[i0];     al[mi][1] = Al[i0 + 288];
                al[mi][2] = Al[i0 + 4]; al[mi][3] = Al[i0 + 292];
            }
            uint32_t bh[4][2], bl[4][2];
#pragma unroll
            for (int ni = 0; ni < 4; ni++) {
                int i0 = (wn * 32 + ni * 8 + g) * 36 + kk + q;
                bh[ni][0] = Bh[i0]; bh[ni][1] = Bh[i0 + 4];
                bl[ni][0] = Bl[i0]; bl[ni][1] = Bl[i0 + 4];
            }
#pragma unroll
            for (int mi = 0; mi < 4; mi++)
#pragma unroll
                for (int ni = 0; ni < 4; ni++) {
                    mma8(acc[mi][ni], ah[mi], bh[ni]);
                    mma8(acc[mi][ni], ah[mi], bl[ni]);
                    mma8(acc[mi][ni], al[mi], bh[ni]);
                }
        }
        if (it + 1 < 8) {
            float* stn = sm + ((it + 1) & 1) * STG1;
            sts_hl(stn, stn + TA, sbase, fa);
            sts_hl(stn + 2 * TA, stn + 3 * TA, sbase, fb);
        }
        __syncthreads();
    }

    float* out = att + (size_t)b * C * S;
#pragma unroll
    for (int mi = 0; mi < 4; mi++) {
        int r = cBase + wm * 64 + mi * 16 + g;
#pragma unroll
        for (int ni = 0; ni < 4; ni++) {
            int cc = sBase + wn * 32 + ni * 8 + 2 * q;
            if (r < C)
                *(float2*)&out[(size_t)r * S + cc] = make_float2(acc[mi][ni][0], acc[mi][ni][1]);
            if (r + 8 < C)
                *(float2*)&out[(size_t)(r + 8) * S + cc] = make_float2(acc[mi][ni][2], acc[mi][ni][3]);
        }
    }
}

// ---------------------------------------------------------------------------
// Softmax over S, in place (proven in R9 baseline)
// ---------------------------------------------------------------------------
__global__ __launch_bounds__(256)
void k_softmax(float* __restrict__ att)
{
    float* p = att + (size_t)blockIdx.x * S;
    const int tid = threadIdx.x;
    float4 v[4];
    float mx = -3.4e38f;
#pragma unroll
    for (int l = 0; l < 4; l++) {
        v[l] = *(const float4*)&p[(size_t)(tid + l * 256) * 4];
        mx = fmaxf(mx, fmaxf(fmaxf(v[l].x, v[l].y), fmaxf(v[l].z, v[l].w)));
    }
    __shared__ float red[8];
#pragma unroll
    for (int o = 16; o; o >>= 1) mx = fmaxf(mx, __shfl_xor_sync(0xffffffffu, mx, o));
    if ((tid & 31) == 0) red[tid >> 5] = mx;
    __syncthreads();
    float m = red[0];
#pragma unroll
    for (int w = 1; w < 8; w++) m = fmaxf(m, red[w]);
    __syncthreads();
    float sum = 0.f;
#pragma unroll
    for (int l = 0; l < 4; l++) {
        v[l].x = __expf(v[l].x - m); v[l].y = __expf(v[l].y - m);
        v[l].z = __expf(v[l].z - m); v[l].w = __expf(v[l].w - m);
        sum += (v[l].x + v[l].y) + (v[l].z + v[l].w);
    }
#pragma unroll
    for (int o = 16; o; o >>= 1) sum += __shfl_xor_sync(0xffffffffu, sum, o);
    if ((tid & 31) == 0) red[tid >> 5] = sum;
    __syncthreads();
    float tot = 0.f;
#pragma unroll
    for (int w = 0; w < 8; w++) tot += red[w];
    const float inv = 1.0f / tot;
#pragma unroll
    for (int l = 0; l < 4; l++) {
        v[l].x *= inv; v[l].y *= inv; v[l].z *= inv; v[l].w *= inv;
        *(float4*)&p[(size_t)(tid + l * 256) * 4] = v[l];
    }
}

// ---------------------------------------------------------------------------
// GEMM2: logits[b][c][d] = sum_s att[b][c][s] * x[b][s][d]   (tf32x3, mma.sync)
// ---------------------------------------------------------------------------
__global__ __launch_bounds__(256)
void k_av(const float* __restrict__ x, const float* __restrict__ att,
          float* __restrict__ logits)
{
    extern __shared__ float sm[];
    const int tid = threadIdx.x, lane = tid & 31, warp = tid >> 5;
    const int wm = warp & 1, wn = warp >> 1;
    const int g = lane >> 2, q = lane & 3;
    const int b = blockIdx.z, cBase = blockIdx.y * 128, dBase = blockIdx.x * 128;

    const float* xb = x + (size_t)b * S * D;
    const float* ab = att + (size_t)b * C * S;

    // A loads: att rows (c), k contiguous
    const int lrow = tid >> 1;
    const int lcol = (tid & 1) * 16;
    const int arow = cBase + lrow;
    const bool aOK = arow < C;
    const float* aSrc = ab + (size_t)(aOK ? arow : 0) * S + lcol;
    const int abase = lrow * 36 + lcol;

    // B loads: x rows (k = s), n = d contiguous
    const int brow = tid >> 3;                // 0..31
    const int bcol = (tid & 7) * 16;          // 0..112
    const float* bSrc = xb + (size_t)brow * D + dBase + bcol;
    const int bbase = brow * 132 + bcol;

    float acc[4][4][4];
#pragma unroll
    for (int i = 0; i < 4; i++)
#pragma unroll
        for (int j = 0; j < 4; j++)
#pragma unroll
            for (int k = 0; k < 4; k++) acc[i][j][k] = 0.0f;

    float4 fa[4], fb[4];
#pragma unroll
    for (int j = 0; j < 4; j++) {
        fa[j] = aOK ? __ldg((const float4*)(aSrc + j * 4)) : make_float4(0.f, 0.f, 0.f, 0.f);
        fb[j] = __ldg((const float4*)(bSrc + j * 4));
    }
    sts_hl(sm, sm + TA, abase, fa);
    sts_hl(sm + 2 * TA, sm + 2 * TA + TB2, bbase, fb);
    __syncthreads();

#pragma unroll 1
    for (int it = 0; it < 128; it++) {
        if (it + 1 < 128) {
            const int kk = (it + 1) * 32;
#pragma unroll
            for (int j = 0; j < 4; j++) {
                fa[j] = aOK ? __ldg((const float4*)(aSrc + kk + j * 4)) : make_float4(0.f, 0.f, 0.f, 0.f);
                fb[j] = __ldg((const float4*)(bSrc + (size_t)kk * D + j * 4));
            }
        }
        const float* st = sm + (it & 1) * STG2;
        const uint32_t* Ah = (const uint32_t*)st;
        const uint32_t* Al = Ah + TA;
        const uint32_t* Bh = Al + TA;
        const uint32_t* Bl = Bh + TB2;

#pragma unroll
        for (int ks = 0; ks < 4; ks++) {
            const int kk = ks * 8;
            uint32_t ah[4][4], al[4][4];
#pragma unroll
            for (int mi = 0; mi < 4; mi++) {
                int i0 = (wm * 64 + mi * 16 + g) * 36 + kk + q;
                ah[mi][0] = Ah[i0];     ah[mi][1] = Ah[i0 + 288];
                ah[mi][2] = Ah[i0 + 4]; ah[mi][3] = Ah[i0 + 292];
                al[mi][0] = Al[i0];     al[mi][1] = Al[i0 + 288];
                al[mi][2] = Al[i0 + 4]; al[mi][3] = Al[i0 + 292];
            }
            uint32_t bh[4][2], bl[4][2];
#pragma unroll
            for (int ni = 0; ni < 4; ni++) {
                int i0 = (kk + q) * 132 + wn * 32 + ni * 8 + g;
                bh[ni][0] = Bh[i0]; bh[ni][1] = Bh[i0 + 528];   // +4 k rows
                bl[ni][0] = Bl[i0]; bl[ni][1] = Bl[i0 + 528];
            }
#pragma unroll
            for (int mi = 0; mi < 4; mi++)
#pragma unroll
                for (int ni = 0; ni < 4; ni++) {
                    mma8(acc[mi][ni], ah[mi], bh[ni]);
                    mma8(acc[mi][ni], ah[mi], bl[ni]);
                    mma8(acc[mi][ni], al[mi], bh[ni]);
                }
        }
        if (it + 1 < 128) {
            float* stn = sm + ((it + 1) & 1) * STG2;
            sts_hl(stn, stn + TA, abase, fa);
            sts_hl(stn + 2 * TA, stn + 2 * TA + TB2, bbase, fb);
        }
        __syncthreads();
    }

    float* out = logits + (size_t)b * C * D;
#pragma unroll
    for (int mi = 0; mi < 4; mi++) {
        int r = cBase + wm * 64 + mi * 16 + g;
#pragma unroll
        for (int ni = 0; ni < 4; ni++) {
            int cc = dBase + wn * 32 + ni * 8 + 2 * q;
            if (r < C)
                *(float2*)&out[(size_t)r * D + cc] = make_float2(acc[mi][ni][0], acc[mi][ni][1]);
            if (r + 8 < C)
                *(float2*)&out[(size_t)(r + 8) * D + cc] = make_float2(acc[mi][ni][2], acc[mi][ni][3]);
        }
    }
}

// ---------------------------------------------------------------------------
extern "C" void kernel_launch(void* const* d_in, const int* in_sizes, int n_in,
                              void* d_out, int out_size)
{
    const float* x = (const float*)d_in[0];  // [B, S, D]
    const float* W = (const float*)d_in[1];  // [C, D]
    float* logits = (float*)d_out;                        // [B, C, D]
    float* att    = (float*)d_out + (size_t)Bsz * C * D;  // [B, C, S]

    cudaFuncSetAttribute(k_scores, cudaFuncAttributeMaxDynamicSharedMemorySize, SM1);
    cudaFuncSetAttribute(k_av, cudaFuncAttributeMaxDynamicSharedMemorySize, SM2);

    k_scores<<<dim3(S / 128, CT, Bsz), 256, SM1>>>(x, W, att);
    k_softmax<<<Bsz * C, 256>>>(att);
    k_av<<<dim3(D / 128, CT, Bsz), 256, SM2>>>(x, att, logits);
}